// round 12
// baseline (speedup 1.0000x reference)
#include <cuda_runtime.h>
#include <cuda_fp16.h>
#include <cstdint>

#define NLAYER 16
#define BATCH 8
#define TLEN 65536
#define NTOT (BATCH*TLEN)        // 524288
#define RES 32
#define KTOT (NLAYER*RES)        // 512

// per-layer coefficient layout (floats), stride 420
#define C_AF0 0
#define C_AF1 32
#define C_AF2 64
#define C_BFA 96
#define C_DF0 128
#define C_DF1 160
#define C_AG0 192
#define C_AG1 224
#define C_AG2 256
#define C_BGA 288
#define C_DG0 320
#define C_DG1 352
#define C_WO  384
#define C_BO  416
#define C_STRIDE 420

__device__ float  g_coef[NLAYER*C_STRIDE];
__device__ __half g_Gh[KTOT*64];     // folded (W_sk1 @ W_s_cat), fp16, layout [j][m]
__device__ float  g_C1[64];          // folded bias into pre-relu
__device__ float  g_bufA[NTOT];
__device__ float  g_bufB[NTOT];
__device__ __half g_gatedH[(size_t)KTOT*NTOT];   // 512 MiB scratch, layout [j][n]

// ---------------------------------------------------------------------------
// Precompute 1: collapse per-layer convs onto the scalar residual stream.
// ---------------------------------------------------------------------------
__global__ void precompute_layer(const float* __restrict__ W_in, const float* __restrict__ b_in,
                                 const float* __restrict__ W_f,  const float* __restrict__ b_f,
                                 const float* __restrict__ W_g,  const float* __restrict__ b_g,
                                 const float* __restrict__ W_o,  const float* __restrict__ b_o)
{
    int i = blockIdx.x;      // layer
    int c = threadIdx.x;     // out channel (32)
    float af[3] = {0,0,0}, df[3] = {0,0,0};
    float ag[3] = {0,0,0}, dg[3] = {0,0,0};
    for (int cin = 0; cin < 32; cin++) {
        float wi = W_in[i*32 + cin];
        float bi = b_in[i*32 + cin];
        #pragma unroll
        for (int k = 0; k < 3; k++) {
            float wf = W_f[((i*32 + c)*32 + cin)*3 + k];
            float wg = W_g[((i*32 + c)*32 + cin)*3 + k];
            af[k] = fmaf(wf, wi, af[k]);
            df[k] = fmaf(wf, bi, df[k]);
            ag[k] = fmaf(wg, wi, ag[k]);
            dg[k] = fmaf(wg, bi, dg[k]);
        }
    }
    float* cf = g_coef + i*C_STRIDE;
    cf[C_AF0+c] = af[0]; cf[C_AF1+c] = af[1]; cf[C_AF2+c] = af[2];
    cf[C_BFA+c] = b_f[i*32 + c] + df[0] + df[1] + df[2];
    cf[C_DF0+c] = df[0]; cf[C_DF1+c] = df[1];
    cf[C_AG0+c] = ag[0]; cf[C_AG1+c] = ag[1]; cf[C_AG2+c] = ag[2];
    cf[C_BGA+c] = b_g[i*32 + c] + dg[0] + dg[1] + dg[2];
    cf[C_DG0+c] = dg[0]; cf[C_DG1+c] = dg[1];
    cf[C_WO +c] = W_o[i*32 + c];
    if (c == 0) cf[C_BO] = b_o[i];
}

// ---------------------------------------------------------------------------
// Precompute 2: fold skip path to fp16 G and fp32 c1.
// ---------------------------------------------------------------------------
__global__ void precompute_skip(const float* __restrict__ W_s,   const float* __restrict__ b_s,
                                const float* __restrict__ W_sk1, const float* __restrict__ b_sk1)
{
    int gid = blockIdx.x*blockDim.x + threadIdx.x;
    if (gid < KTOT*64) {
        int j = gid >> 6, m = gid & 63;
        int i = j >> 5, c = j & 31;
        float acc = 0.f;
        for (int o = 0; o < 64; o++)
            acc = fmaf(W_sk1[m*64 + o], W_s[(i*64 + o)*32 + c], acc);
        g_Gh[j*64 + m] = __float2half_rn(acc);
    }
    if (gid < 64) {
        int m = gid;
        float acc = b_sk1[m];
        for (int o = 0; o < 64; o++) {
            float bs = 0.f;
            for (int i2 = 0; i2 < NLAYER; i2++) bs += b_s[i2*64 + o];
            acc = fmaf(W_sk1[m*64 + o], bs, acc);
        }
        g_C1[m] = acc;
    }
}

// ---------------------------------------------------------------------------
// Phase A: one kernel per layer on the collapsed rank-1 form.
// gated = tanh(pf)*sigmoid(pg) fused: (ef-1)*eg / ((ef+1)*(eg+1)), 3 MUFU.
// ---------------------------------------------------------------------------
#define AU 4
__global__ void __launch_bounds__(256) layer_kernel(const float* __restrict__ x, int layer, int d)
{
    __shared__ float cf[C_STRIDE];
    {
        const float* gc = g_coef + layer*C_STRIDE;
        for (int idx = threadIdx.x; idx < C_STRIDE; idx += 256) cf[idx] = gc[idx];
    }
    __syncthreads();

    const float* in = (layer == 0) ? x : ((layer & 1) ? g_bufA : g_bufB);
    float* out = (layer & 1) ? g_bufB : g_bufA;
    __half* gp = g_gatedH + (size_t)layer*RES*NTOT;

    int base = blockIdx.x*(256*AU) + threadIdx.x;

    float o0[AU], o1[AU], o2[AU], acc[AU];
    int tt[AU];
    #pragma unroll
    for (int u = 0; u < AU; u++) {
        int n = base + u*256;
        int t = n & (TLEN - 1);
        tt[u] = t;
        o2[u] = in[n];
        o1[u] = (t >= d)   ? in[n - d]   : 0.f;
        o0[u] = (t >= 2*d) ? in[n - 2*d] : 0.f;
        acc[u] = 0.f;
    }
    float bo = cf[C_BO];

    #pragma unroll 4
    for (int c = 0; c < RES; c++) {
        float af0 = cf[C_AF0+c], af1 = cf[C_AF1+c], af2 = cf[C_AF2+c], bfa = cf[C_BFA+c];
        float ag0 = cf[C_AG0+c], ag1 = cf[C_AG1+c], ag2 = cf[C_AG2+c], bga = cf[C_BGA+c];
        float wo  = cf[C_WO+c];
        __half* gout = gp + (size_t)c*NTOT;
        #pragma unroll
        for (int u = 0; u < AU; u++) {
            float pf = fmaf(af0, o0[u], fmaf(af1, o1[u], fmaf(af2, o2[u], bfa)));
            float pg = fmaf(ag0, o0[u], fmaf(ag1, o1[u], fmaf(ag2, o2[u], bga)));
            if (tt[u] < 2*d) {
                pf -= cf[C_DF0+c]; pg -= cf[C_DG0+c];
                if (tt[u] < d) { pf -= cf[C_DF1+c]; pg -= cf[C_DG1+c]; }
            }
            pf = fminf(fmaxf(pf, -15.f), 15.f);
            pg = fminf(fmaxf(pg, -30.f), 30.f);
            float ef = __expf(2.f*pf);
            float eg = __expf(pg);
            float gt = __fdividef((ef - 1.f)*eg, (ef + 1.f)*(eg + 1.f));
            gout[base + u*256] = __float2half_rn(gt);
            acc[u] = fmaf(wo, gt, acc[u]);
        }
    }
    #pragma unroll
    for (int u = 0; u < AU; u++) {
        int n = base + u*256;
        out[n] = o2[u] + acc[u] + bo;
    }
}

// ---------------------------------------------------------------------------
// Phase B: D[128 samples, 64 m] per block = X[samples,512] @ G[512,64],
// via HMMA m16n8k16 (fp16 in, fp32 acc), fused relu/head/exp epilogue.
// smem tiles are padded so ldmatrix row-stride ≡ 4 words (mod 32): conflict-free.
// ---------------------------------------------------------------------------
#define NT 128
#define KC 64
#define XPITCH 136   // halfs per row (272B; 68 words ≡ 4 mod 32)
#define GPITCH 72    // halfs per row (144B; 36 words ≡ 4 mod 32)

__device__ __forceinline__ uint32_t smem_u32(const void* p) {
    uint32_t a;
    asm("{ .reg .u64 t; cvta.to.shared.u64 t, %1; cvt.u32.u64 %0, t; }" : "=r"(a) : "l"(p));
    return a;
}

__global__ void __launch_bounds__(256) phaseB_kernel(const float* __restrict__ W_sk2,
                                                     const float* __restrict__ b_sk2,
                                                     float* __restrict__ outp)
{
    __shared__ __align__(16) __half sX[KC*XPITCH];   // 17408 B
    __shared__ __align__(16) __half sG[KC*GPITCH];   //  9216 B

    int tid  = threadIdx.x;
    int n0   = blockIdx.x * NT;
    int warp = tid >> 5, lane = tid & 31;
    int grp  = lane >> 2, tig = lane & 3;
    int s0   = warp * 16;              // this warp's 16 samples

    float c[8][4];
    #pragma unroll
    for (int a = 0; a < 8; a++)
        #pragma unroll
        for (int b = 0; b < 4; b++) c[a][b] = 0.f;

    // per-lane ldmatrix addresses
    int i8 = lane & 7, seg = lane >> 3;
    // A (samples x k) from sX[k][n]:  seg0:(k0+i, s0) seg1:(k0+i, s0+8) seg2:(k0+8+i, s0) seg3:(k0+8+i, s0+8)
    uint32_t aAddr = smem_u32(sX) +
        (uint32_t)(((i8 + (seg >> 1)*8)*XPITCH + s0 + (seg & 1)*8) * 2);
    // B (k x m) from sG[k][m]:       seg0:(k0+i, 0)  seg1:(k0+8+i, 0)  seg2:(k0+i, 8)  seg3:(k0+8+i, 8)
    uint32_t bAddr = smem_u32(sG) +
        (uint32_t)(((i8 + (seg & 1)*8)*GPITCH + (seg >> 1)*8) * 2);

    for (int jb = 0; jb < KTOT; jb += KC) {
        // stage X tile: 64 k-rows x 128 samples, coalesced float4
        #pragma unroll
        for (int it = 0; it < 4; it++) {
            int idx = it*256 + tid;
            int k = idx >> 4, noct = idx & 15;
            float4 v = *reinterpret_cast<const float4*>(
                &g_gatedH[(size_t)(jb + k)*NTOT + n0 + noct*8]);
            *reinterpret_cast<float4*>(&sX[k*XPITCH + noct*8]) = v;
        }
        // stage G tile: 64 k-rows x 64 m
        #pragma unroll
        for (int it = 0; it < 2; it++) {
            int idx = it*256 + tid;
            int k = idx >> 3, moct = idx & 7;
            float4 v = *reinterpret_cast<const float4*>(&g_Gh[(jb + k)*64 + moct*8]);
            *reinterpret_cast<float4*>(&sG[k*GPITCH + moct*8]) = v;
        }
        __syncthreads();

        #pragma unroll
        for (int ks = 0; ks < 4; ks++) {        // 4 k-steps of 16
            uint32_t a0, a1, a2, a3;
            asm volatile("ldmatrix.sync.aligned.m8n8.x4.trans.shared.b16 {%0,%1,%2,%3}, [%4];"
                         : "=r"(a0), "=r"(a1), "=r"(a2), "=r"(a3)
                         : "r"(aAddr + (uint32_t)(ks*16*XPITCH*2)));
            #pragma unroll
            for (int mp = 0; mp < 4; mp++) {    // m-pairs: tiles 2mp, 2mp+1
                uint32_t b0, b1, b2, b3;
                asm volatile("ldmatrix.sync.aligned.m8n8.x4.trans.shared.b16 {%0,%1,%2,%3}, [%4];"
                             : "=r"(b0), "=r"(b1), "=r"(b2), "=r"(b3)
                             : "r"(bAddr + (uint32_t)((ks*16*GPITCH + mp*16)*2)));
                asm volatile("mma.sync.aligned.m16n8k16.row.col.f32.f16.f16.f32 "
                             "{%0,%1,%2,%3}, {%4,%5,%6,%7}, {%8,%9}, {%0,%1,%2,%3};"
                             : "+f"(c[2*mp][0]), "+f"(c[2*mp][1]), "+f"(c[2*mp][2]), "+f"(c[2*mp][3])
                             : "r"(a0), "r"(a1), "r"(a2), "r"(a3), "r"(b0), "r"(b1));
                asm volatile("mma.sync.aligned.m16n8k16.row.col.f32.f16.f16.f32 "
                             "{%0,%1,%2,%3}, {%4,%5,%6,%7}, {%8,%9}, {%0,%1,%2,%3};"
                             : "+f"(c[2*mp+1][0]), "+f"(c[2*mp+1][1]), "+f"(c[2*mp+1][2]), "+f"(c[2*mp+1][3])
                             : "r"(a0), "r"(a1), "r"(a2), "r"(a3), "r"(b2), "r"(b3));
            }
        }
        __syncthreads();
    }

    // epilogue: +c1, relu, project to 2 channels, reduce across tig lanes
    float pa0 = 0.f, pa1 = 0.f, pb0 = 0.f, pb1 = 0.f;
    #pragma unroll
    for (int mt = 0; mt < 8; mt++) {
        int m = mt*8 + tig*2;
        float c1a = g_C1[m],     c1b = g_C1[m+1];
        float w0a = W_sk2[m],    w0b = W_sk2[m+1];
        float w1a = W_sk2[64+m], w1b = W_sk2[64+m+1];
        float v;
        v = fmaxf(c[mt][0] + c1a, 0.f); pa0 = fmaf(w0a, v, pa0); pa1 = fmaf(w1a, v, pa1);
        v = fmaxf(c[mt][1] + c1b, 0.f); pa0 = fmaf(w0b, v, pa0); pa1 = fmaf(w1b, v, pa1);
        v = fmaxf(c[mt][2] + c1a, 0.f); pb0 = fmaf(w0a, v, pb0); pb1 = fmaf(w1a, v, pb1);
        v = fmaxf(c[mt][3] + c1b, 0.f); pb0 = fmaf(w0b, v, pb0); pb1 = fmaf(w1b, v, pb1);
    }
    #pragma unroll
    for (int off = 1; off <= 2; off <<= 1) {
        pa0 += __shfl_xor_sync(0xFFFFFFFFu, pa0, off);
        pa1 += __shfl_xor_sync(0xFFFFFFFFu, pa1, off);
        pb0 += __shfl_xor_sync(0xFFFFFFFFu, pb0, off);
        pb1 += __shfl_xor_sync(0xFFFFFFFFu, pb1, off);
    }
    if (tig == 0) {
        int na = n0 + s0 + grp;
        int nb = na + 8;
        outp[na]        = pa0 + b_sk2[0];
        outp[NTOT + na] = __expf(0.5f*(pa1 + b_sk2[1]));
        outp[nb]        = pb0 + b_sk2[0];
        outp[NTOT + nb] = __expf(0.5f*(pb1 + b_sk2[1]));
    }
}

// ---------------------------------------------------------------------------
extern "C" void kernel_launch(void* const* d_in, const int* in_sizes, int n_in,
                              void* d_out, int out_size)
{
    const float* x     = (const float*)d_in[0];
    const float* W_in  = (const float*)d_in[1];
    const float* b_in  = (const float*)d_in[2];
    const float* W_f   = (const float*)d_in[3];
    const float* b_f   = (const float*)d_in[4];
    const float* W_g   = (const float*)d_in[5];
    const float* b_g   = (const float*)d_in[6];
    const float* W_s   = (const float*)d_in[7];
    const float* b_s   = (const float*)d_in[8];
    const float* W_o   = (const float*)d_in[9];
    const float* b_o   = (const float*)d_in[10];
    const float* W_sk1 = (const float*)d_in[11];
    const float* b_sk1 = (const float*)d_in[12];
    const float* W_sk2 = (const float*)d_in[13];
    const float* b_sk2 = (const float*)d_in[14];
    float* outp = (float*)d_out;

    precompute_layer<<<NLAYER, 32>>>(W_in, b_in, W_f, b_f, W_g, b_g, W_o, b_o);
    precompute_skip<<<128, 256>>>(W_s, b_s, W_sk1, b_sk1);

    for (int i = 0; i < NLAYER; i++) {
        int d = 1 << (i & 7);
        layer_kernel<<<NTOT/(256*AU), 256>>>(x, i, d);
    }
    phaseB_kernel<<<NTOT/NT, 256>>>(W_sk2, b_sk2, outp);
}

// round 14
// speedup vs baseline: 1.2944x; 1.2944x over previous
#include <cuda_runtime.h>
#include <cuda_fp16.h>
#include <cstdint>

#define NLAYER 16
#define BATCH 8
#define TLEN 65536
#define NTOT (BATCH*TLEN)        // 524288
#define RES 32
#define KTOT (NLAYER*RES)        // 512

// per-layer coefficient layout (floats), stride 420
// NOTE: all *G* entries are pre-halved (sigmoid-via-tanh trick)
#define C_AF0 0
#define C_AF1 32
#define C_AF2 64
#define C_BFA 96
#define C_DF0 128
#define C_DF1 160
#define C_AG0 192
#define C_AG1 224
#define C_AG2 256
#define C_BGA 288
#define C_DG0 320
#define C_DG1 352
#define C_WO  384
#define C_BO  416
#define C_STRIDE 420

__device__ float  g_coef[NLAYER*C_STRIDE];
__device__ __half g_Gh[KTOT*64];     // folded (W_sk1 @ W_s_cat), fp16, layout [j][m]
__device__ float  g_C1[64];          // folded bias into pre-relu
__device__ float  g_bufA[NTOT];
__device__ float  g_bufB[NTOT];
__device__ __half g_gatedH[(size_t)KTOT*NTOT];   // 512 MiB scratch, layout [j][n]

// ---------------------------------------------------------------------------
// Precompute 1: collapse per-layer convs onto the scalar residual stream.
// G-path coefficients are stored pre-multiplied by 0.5.
// ---------------------------------------------------------------------------
__global__ void precompute_layer(const float* __restrict__ W_in, const float* __restrict__ b_in,
                                 const float* __restrict__ W_f,  const float* __restrict__ b_f,
                                 const float* __restrict__ W_g,  const float* __restrict__ b_g,
                                 const float* __restrict__ W_o,  const float* __restrict__ b_o)
{
    int i = blockIdx.x;      // layer
    int c = threadIdx.x;     // out channel (32)
    float af[3] = {0,0,0}, df[3] = {0,0,0};
    float ag[3] = {0,0,0}, dg[3] = {0,0,0};
    for (int cin = 0; cin < 32; cin++) {
        float wi = W_in[i*32 + cin];
        float bi = b_in[i*32 + cin];
        #pragma unroll
        for (int k = 0; k < 3; k++) {
            float wf = W_f[((i*32 + c)*32 + cin)*3 + k];
            float wg = W_g[((i*32 + c)*32 + cin)*3 + k];
            af[k] = fmaf(wf, wi, af[k]);
            df[k] = fmaf(wf, bi, df[k]);
            ag[k] = fmaf(wg, wi, ag[k]);
            dg[k] = fmaf(wg, bi, dg[k]);
        }
    }
    float* cf = g_coef + i*C_STRIDE;
    cf[C_AF0+c] = af[0]; cf[C_AF1+c] = af[1]; cf[C_AF2+c] = af[2];
    cf[C_BFA+c] = b_f[i*32 + c] + df[0] + df[1] + df[2];
    cf[C_DF0+c] = df[0]; cf[C_DF1+c] = df[1];
    cf[C_AG0+c] = 0.5f*ag[0]; cf[C_AG1+c] = 0.5f*ag[1]; cf[C_AG2+c] = 0.5f*ag[2];
    cf[C_BGA+c] = 0.5f*(b_g[i*32 + c] + dg[0] + dg[1] + dg[2]);
    cf[C_DG0+c] = 0.5f*dg[0]; cf[C_DG1+c] = 0.5f*dg[1];
    cf[C_WO +c] = W_o[i*32 + c];
    if (c == 0) cf[C_BO] = b_o[i];
}

// ---------------------------------------------------------------------------
// Precompute 2: fold skip path to fp16 G and fp32 c1.
// ---------------------------------------------------------------------------
__global__ void precompute_skip(const float* __restrict__ W_s,   const float* __restrict__ b_s,
                                const float* __restrict__ W_sk1, const float* __restrict__ b_sk1)
{
    int gid = blockIdx.x*blockDim.x + threadIdx.x;
    if (gid < KTOT*64) {
        int j = gid >> 6, m = gid & 63;
        int i = j >> 5, c = j & 31;
        float acc = 0.f;
        for (int o = 0; o < 64; o++)
            acc = fmaf(W_sk1[m*64 + o], W_s[(i*64 + o)*32 + c], acc);
        g_Gh[j*64 + m] = __float2half_rn(acc);
    }
    if (gid < 64) {
        int m = gid;
        float acc = b_sk1[m];
        for (int o = 0; o < 64; o++) {
            float bs = 0.f;
            for (int i2 = 0; i2 < NLAYER; i2++) bs += b_s[i2*64 + o];
            acc = fmaf(W_sk1[m*64 + o], bs, acc);
        }
        g_C1[m] = acc;
    }
}

// ---------------------------------------------------------------------------
// Phase A: one kernel per layer on the collapsed rank-1 form.
// gated = tanh(pf) * (0.5*tanh(pg_half) + 0.5)  — 2 HW MUFU ops, no divide.
// Thread owns 4 CONTIGUOUS samples -> packed 8B fp16 stores per channel.
// ---------------------------------------------------------------------------
__device__ __forceinline__ float tanh_hw(float x) {
    float y;
    asm("tanh.approx.f32 %0, %1;" : "=f"(y) : "f"(x));
    return y;
}

#define AU 4
__global__ void __launch_bounds__(256) layer_kernel(const float* __restrict__ x, int layer, int d)
{
    __shared__ float cf[C_STRIDE];
    {
        const float* gc = g_coef + layer*C_STRIDE;
        for (int idx = threadIdx.x; idx < C_STRIDE; idx += 256) cf[idx] = gc[idx];
    }
    __syncthreads();

    const float* in = (layer == 0) ? x : ((layer & 1) ? g_bufA : g_bufB);
    float* out = (layer & 1) ? g_bufB : g_bufA;
    __half* gp = g_gatedH + (size_t)layer*RES*NTOT;

    int base = (blockIdx.x*256 + threadIdx.x)*AU;   // contiguous quad
    int tbase = base & (TLEN - 1);                  // quad never crosses batch row

    float o0[AU], o1[AU], o2[AU], acc[AU];
    {
        float4 v = *reinterpret_cast<const float4*>(&in[base]);
        o2[0] = v.x; o2[1] = v.y; o2[2] = v.z; o2[3] = v.w;
    }
    #pragma unroll
    for (int u = 0; u < AU; u++) {
        int n = base + u, t = tbase + u;
        o1[u] = (t >= d)   ? in[n - d]   : 0.f;
        o0[u] = (t >= 2*d) ? in[n - 2*d] : 0.f;
        acc[u] = 0.f;
    }
    float bo = cf[C_BO];
    bool edge = (tbase < 2*d);   // rare

    #pragma unroll 4
    for (int c = 0; c < RES; c++) {
        float af0 = cf[C_AF0+c], af1 = cf[C_AF1+c], af2 = cf[C_AF2+c], bfa = cf[C_BFA+c];
        float ag0 = cf[C_AG0+c], ag1 = cf[C_AG1+c], ag2 = cf[C_AG2+c], bga = cf[C_BGA+c];
        float wo  = cf[C_WO+c];
        float gt[AU];
        #pragma unroll
        for (int u = 0; u < AU; u++) {
            float pf = fmaf(af0, o0[u], fmaf(af1, o1[u], fmaf(af2, o2[u], bfa)));
            float pg = fmaf(ag0, o0[u], fmaf(ag1, o1[u], fmaf(ag2, o2[u], bga)));
            if (edge) {
                int t = tbase + u;
                if (t < 2*d) { pf -= cf[C_DF0+c]; pg -= cf[C_DG0+c]; }
                if (t < d)   { pf -= cf[C_DF1+c]; pg -= cf[C_DG1+c]; }
            }
            float tf = tanh_hw(pf);
            float tg = tanh_hw(pg);               // pg already halved via coefs
            float sg = fmaf(0.5f, tg, 0.5f);
            gt[u] = tf * sg;
            acc[u] = fmaf(wo, gt[u], acc[u]);
        }
        __half2 h01 = __floats2half2_rn(gt[0], gt[1]);
        __half2 h23 = __floats2half2_rn(gt[2], gt[3]);
        uint2 pk;
        pk.x = *reinterpret_cast<uint32_t*>(&h01);
        pk.y = *reinterpret_cast<uint32_t*>(&h23);
        *reinterpret_cast<uint2*>(&gp[(size_t)c*NTOT + base]) = pk;
    }
    {
        float4 v;
        v.x = o2[0] + acc[0] + bo;
        v.y = o2[1] + acc[1] + bo;
        v.z = o2[2] + acc[2] + bo;
        v.w = o2[3] + acc[3] + bo;
        *reinterpret_cast<float4*>(&out[base]) = v;
    }
}

// ---------------------------------------------------------------------------
// Phase B: D[128 samples, 64 m] per block = X[samples,512] @ G[512,64],
// via HMMA m16n8k16 (fp16 in, fp32 acc), fused relu/head/exp epilogue.
// ---------------------------------------------------------------------------
#define NT 128
#define KC 64
#define XPITCH 136   // halfs per row (272B; 68 words ≡ 4 mod 32)
#define GPITCH 72    // halfs per row (144B; 36 words ≡ 4 mod 32)

__device__ __forceinline__ uint32_t smem_u32(const void* p) {
    uint32_t a;
    asm("{ .reg .u64 t; cvta.to.shared.u64 t, %1; cvt.u32.u64 %0, t; }" : "=r"(a) : "l"(p));
    return a;
}

__global__ void __launch_bounds__(256) phaseB_kernel(const float* __restrict__ W_sk2,
                                                     const float* __restrict__ b_sk2,
                                                     float* __restrict__ outp)
{
    __shared__ __align__(16) __half sX[KC*XPITCH];   // 17408 B
    __shared__ __align__(16) __half sG[KC*GPITCH];   //  9216 B

    int tid  = threadIdx.x;
    int n0   = blockIdx.x * NT;
    int warp = tid >> 5, lane = tid & 31;
    int grp  = lane >> 2, tig = lane & 3;
    int s0   = warp * 16;              // this warp's 16 samples

    float c[8][4];
    #pragma unroll
    for (int a = 0; a < 8; a++)
        #pragma unroll
        for (int b = 0; b < 4; b++) c[a][b] = 0.f;

    int i8 = lane & 7, seg = lane >> 3;
    uint32_t aAddr = smem_u32(sX) +
        (uint32_t)(((i8 + (seg >> 1)*8)*XPITCH + s0 + (seg & 1)*8) * 2);
    uint32_t bAddr = smem_u32(sG) +
        (uint32_t)(((i8 + (seg & 1)*8)*GPITCH + (seg >> 1)*8) * 2);

    for (int jb = 0; jb < KTOT; jb += KC) {
        #pragma unroll
        for (int it = 0; it < 4; it++) {
            int idx = it*256 + tid;
            int k = idx >> 4, noct = idx & 15;
            float4 v = *reinterpret_cast<const float4*>(
                &g_gatedH[(size_t)(jb + k)*NTOT + n0 + noct*8]);
            *reinterpret_cast<float4*>(&sX[k*XPITCH + noct*8]) = v;
        }
        #pragma unroll
        for (int it = 0; it < 2; it++) {
            int idx = it*256 + tid;
            int k = idx >> 3, moct = idx & 7;
            float4 v = *reinterpret_cast<const float4*>(&g_Gh[(jb + k)*64 + moct*8]);
            *reinterpret_cast<float4*>(&sG[k*GPITCH + moct*8]) = v;
        }
        __syncthreads();

        #pragma unroll
        for (int ks = 0; ks < 4; ks++) {
            uint32_t a0, a1, a2, a3;
            asm volatile("ldmatrix.sync.aligned.m8n8.x4.trans.shared.b16 {%0,%1,%2,%3}, [%4];"
                         : "=r"(a0), "=r"(a1), "=r"(a2), "=r"(a3)
                         : "r"(aAddr + (uint32_t)(ks*16*XPITCH*2)));
            #pragma unroll
            for (int mp = 0; mp < 4; mp++) {
                uint32_t b0, b1, b2, b3;
                asm volatile("ldmatrix.sync.aligned.m8n8.x4.trans.shared.b16 {%0,%1,%2,%3}, [%4];"
                             : "=r"(b0), "=r"(b1), "=r"(b2), "=r"(b3)
                             : "r"(bAddr + (uint32_t)((ks*16*GPITCH + mp*16)*2)));
                asm volatile("mma.sync.aligned.m16n8k16.row.col.f32.f16.f16.f32 "
                             "{%0,%1,%2,%3}, {%4,%5,%6,%7}, {%8,%9}, {%0,%1,%2,%3};"
                             : "+f"(c[2*mp][0]), "+f"(c[2*mp][1]), "+f"(c[2*mp][2]), "+f"(c[2*mp][3])
                             : "r"(a0), "r"(a1), "r"(a2), "r"(a3), "r"(b0), "r"(b1));
                asm volatile("mma.sync.aligned.m16n8k16.row.col.f32.f16.f16.f32 "
                             "{%0,%1,%2,%3}, {%4,%5,%6,%7}, {%8,%9}, {%0,%1,%2,%3};"
                             : "+f"(c[2*mp+1][0]), "+f"(c[2*mp+1][1]), "+f"(c[2*mp+1][2]), "+f"(c[2*mp+1][3])
                             : "r"(a0), "r"(a1), "r"(a2), "r"(a3), "r"(b2), "r"(b3));
            }
        }
        __syncthreads();
    }

    float pa0 = 0.f, pa1 = 0.f, pb0 = 0.f, pb1 = 0.f;
    #pragma unroll
    for (int mt = 0; mt < 8; mt++) {
        int m = mt*8 + tig*2;
        float c1a = g_C1[m],     c1b = g_C1[m+1];
        float w0a = W_sk2[m],    w0b = W_sk2[m+1];
        float w1a = W_sk2[64+m], w1b = W_sk2[64+m+1];
        float v;
        v = fmaxf(c[mt][0] + c1a, 0.f); pa0 = fmaf(w0a, v, pa0); pa1 = fmaf(w1a, v, pa1);
        v = fmaxf(c[mt][1] + c1b, 0.f); pa0 = fmaf(w0b, v, pa0); pa1 = fmaf(w1b, v, pa1);
        v = fmaxf(c[mt][2] + c1a, 0.f); pb0 = fmaf(w0a, v, pb0); pb1 = fmaf(w1a, v, pb1);
        v = fmaxf(c[mt][3] + c1b, 0.f); pb0 = fmaf(w0b, v, pb0); pb1 = fmaf(w1b, v, pb1);
    }
    #pragma unroll
    for (int off = 1; off <= 2; off <<= 1) {
        pa0 += __shfl_xor_sync(0xFFFFFFFFu, pa0, off);
        pa1 += __shfl_xor_sync(0xFFFFFFFFu, pa1, off);
        pb0 += __shfl_xor_sync(0xFFFFFFFFu, pb0, off);
        pb1 += __shfl_xor_sync(0xFFFFFFFFu, pb1, off);
    }
    if (tig == 0) {
        int na = n0 + s0 + grp;
        int nb = na + 8;
        outp[na]        = pa0 + b_sk2[0];
        outp[NTOT + na] = __expf(0.5f*(pa1 + b_sk2[1]));
        outp[nb]        = pb0 + b_sk2[0];
        outp[NTOT + nb] = __expf(0.5f*(pb1 + b_sk2[1]));
    }
}

// ---------------------------------------------------------------------------
extern "C" void kernel_launch(void* const* d_in, const int* in_sizes, int n_in,
                              void* d_out, int out_size)
{
    const float* x     = (const float*)d_in[0];
    const float* W_in  = (const float*)d_in[1];
    const float* b_in  = (const float*)d_in[2];
    const float* W_f   = (const float*)d_in[3];
    const float* b_f   = (const float*)d_in[4];
    const float* W_g   = (const float*)d_in[5];
    const float* b_g   = (const float*)d_in[6];
    const float* W_s   = (const float*)d_in[7];
    const float* b_s   = (const float*)d_in[8];
    const float* W_o   = (const float*)d_in[9];
    const float* b_o   = (const float*)d_in[10];
    const float* W_sk1 = (const float*)d_in[11];
    const float* b_sk1 = (const float*)d_in[12];
    const float* W_sk2 = (const float*)d_in[13];
    const float* b_sk2 = (const float*)d_in[14];
    float* outp = (float*)d_out;

    precompute_layer<<<NLAYER, 32>>>(W_in, b_in, W_f, b_f, W_g, b_g, W_o, b_o);
    precompute_skip<<<128, 256>>>(W_s, b_s, W_sk1, b_sk1);

    for (int i = 0; i < NLAYER; i++) {
        int d = 1 << (i & 7);
        layer_kernel<<<NTOT/(256*AU), 256>>>(x, i, d);
    }
    phaseB_kernel<<<NTOT/NT, 256>>>(W_sk2, b_sk2, outp);
}

// round 15
// speedup vs baseline: 1.6944x; 1.3090x over previous
#include <cuda_runtime.h>
#include <cuda_fp16.h>
#include <cstdint>

#define NLAYER 16
#define BATCH 8
#define TLEN 65536
#define NTOT (BATCH*TLEN)        // 524288
#define RES 32
#define KTOT (NLAYER*RES)        // 512

typedef unsigned long long ull;

// per-layer coefficient layout (floats), stride 420
// NOTE: all *G* entries are pre-halved (sigmoid-via-tanh trick)
#define C_AF0 0
#define C_AF1 32
#define C_AF2 64
#define C_BFA 96
#define C_DF0 128
#define C_DF1 160
#define C_AG0 192
#define C_AG1 224
#define C_AG2 256
#define C_BGA 288
#define C_DG0 320
#define C_DG1 352
#define C_WO  384
#define C_BO  416
#define C_STRIDE 420

__device__ float  g_coef[NLAYER*C_STRIDE];
__device__ __half g_Gh[KTOT*64];     // folded (W_sk1 @ W_s_cat), fp16, layout [j][m]
__device__ float  g_C1[64];          // folded bias into pre-relu
__device__ float  g_bufA[NTOT];
__device__ float  g_bufB[NTOT];
__device__ __half g_gatedH[(size_t)KTOT*NTOT];   // 512 MiB scratch, layout [j][n]

// ---------------------------------------------------------------------------
// Precompute 1: collapse per-layer convs onto the scalar residual stream.
// ---------------------------------------------------------------------------
__global__ void precompute_layer(const float* __restrict__ W_in, const float* __restrict__ b_in,
                                 const float* __restrict__ W_f,  const float* __restrict__ b_f,
                                 const float* __restrict__ W_g,  const float* __restrict__ b_g,
                                 const float* __restrict__ W_o,  const float* __restrict__ b_o)
{
    int i = blockIdx.x;      // layer
    int c = threadIdx.x;     // out channel (32)
    float af[3] = {0,0,0}, df[3] = {0,0,0};
    float ag[3] = {0,0,0}, dg[3] = {0,0,0};
    for (int cin = 0; cin < 32; cin++) {
        float wi = W_in[i*32 + cin];
        float bi = b_in[i*32 + cin];
        #pragma unroll
        for (int k = 0; k < 3; k++) {
            float wf = W_f[((i*32 + c)*32 + cin)*3 + k];
            float wg = W_g[((i*32 + c)*32 + cin)*3 + k];
            af[k] = fmaf(wf, wi, af[k]);
            df[k] = fmaf(wf, bi, df[k]);
            ag[k] = fmaf(wg, wi, ag[k]);
            dg[k] = fmaf(wg, bi, dg[k]);
        }
    }
    float* cf = g_coef + i*C_STRIDE;
    cf[C_AF0+c] = af[0]; cf[C_AF1+c] = af[1]; cf[C_AF2+c] = af[2];
    cf[C_BFA+c] = b_f[i*32 + c] + df[0] + df[1] + df[2];
    cf[C_DF0+c] = df[0]; cf[C_DF1+c] = df[1];
    cf[C_AG0+c] = 0.5f*ag[0]; cf[C_AG1+c] = 0.5f*ag[1]; cf[C_AG2+c] = 0.5f*ag[2];
    cf[C_BGA+c] = 0.5f*(b_g[i*32 + c] + dg[0] + dg[1] + dg[2]);
    cf[C_DG0+c] = 0.5f*dg[0]; cf[C_DG1+c] = 0.5f*dg[1];
    cf[C_WO +c] = W_o[i*32 + c];
    if (c == 0) cf[C_BO] = b_o[i];
}

// ---------------------------------------------------------------------------
// Precompute 2: fold skip path to fp16 G and fp32 c1.
// ---------------------------------------------------------------------------
__global__ void precompute_skip(const float* __restrict__ W_s,   const float* __restrict__ b_s,
                                const float* __restrict__ W_sk1, const float* __restrict__ b_sk1)
{
    int gid = blockIdx.x*blockDim.x + threadIdx.x;
    if (gid < KTOT*64) {
        int j = gid >> 6, m = gid & 63;
        int i = j >> 5, c = j & 31;
        float acc = 0.f;
        for (int o = 0; o < 64; o++)
            acc = fmaf(W_sk1[m*64 + o], W_s[(i*64 + o)*32 + c], acc);
        g_Gh[j*64 + m] = __float2half_rn(acc);
    }
    if (gid < 64) {
        int m = gid;
        float acc = b_sk1[m];
        for (int o = 0; o < 64; o++) {
            float bs = 0.f;
            for (int i2 = 0; i2 < NLAYER; i2++) bs += b_s[i2*64 + o];
            acc = fmaf(W_sk1[m*64 + o], bs, acc);
        }
        g_C1[m] = acc;
    }
}

// ---------------------------------------------------------------------------
// Phase A helpers
// ---------------------------------------------------------------------------
__device__ __forceinline__ float tanh_hw(float x) {
    float y;
    asm("tanh.approx.f32 %0, %1;" : "=f"(y) : "f"(x));
    return y;
}
__device__ __forceinline__ ull pack2(float a, float b) {
    ull r;
    asm("mov.b64 %0, {%1,%2};" : "=l"(r) : "r"(__float_as_uint(a)), "r"(__float_as_uint(b)));
    return r;
}
__device__ __forceinline__ void unpack2(ull p, float& a, float& b) {
    unsigned lo, hi;
    asm("mov.b64 {%0,%1}, %2;" : "=r"(lo), "=r"(hi) : "l"(p));
    a = __uint_as_float(lo); b = __uint_as_float(hi);
}
__device__ __forceinline__ ull fma2(ull a, ull b, ull c) {
    ull d;
    asm("fma.rn.f32x2 %0, %1, %2, %3;" : "=l"(d) : "l"(a), "l"(b), "l"(c));
    return d;
}

// ---------------------------------------------------------------------------
// Phase A: collapsed rank-1 form, f32x2 packed FMAs (coefs duplicated in smem),
// gated = tanh(pf) * (0.5*tanh(pg_half) + 0.5), packed 8B fp16 stores.
// ---------------------------------------------------------------------------
#define AU 4
__global__ void __launch_bounds__(256) layer_kernel(const float* __restrict__ x, int layer, int d)
{
    __shared__ __align__(8) float2 cf2[C_STRIDE];   // each coef duplicated in .x/.y
    {
        const float* gc = g_coef + layer*C_STRIDE;
        for (int idx = threadIdx.x; idx < C_STRIDE; idx += 256) {
            float v = gc[idx];
            cf2[idx] = make_float2(v, v);
        }
    }
    __syncthreads();

    const float* in = (layer == 0) ? x : ((layer & 1) ? g_bufA : g_bufB);
    float* out = (layer & 1) ? g_bufB : g_bufA;
    __half* gp = g_gatedH + (size_t)layer*RES*NTOT;

    int base = (blockIdx.x*256 + threadIdx.x)*AU;   // contiguous quad
    int tbase = base & (TLEN - 1);                  // quad never crosses batch row

    float o0[AU], o1[AU], o2[AU], acc[AU];
    {
        float4 v = *reinterpret_cast<const float4*>(&in[base]);
        o2[0] = v.x; o2[1] = v.y; o2[2] = v.z; o2[3] = v.w;
    }
    #pragma unroll
    for (int u = 0; u < AU; u++) {
        int n = base + u, t = tbase + u;
        o1[u] = (t >= d)   ? in[n - d]   : 0.f;
        o0[u] = (t >= 2*d) ? in[n - 2*d] : 0.f;
        acc[u] = 0.f;
    }
    float bo = cf2[C_BO].x;
    bool edge = (tbase < 2*d);   // rare

    if (!edge) {
        ull o0p[2], o1p[2], o2p[2];
        #pragma unroll
        for (int p = 0; p < 2; p++) {
            o0p[p] = pack2(o0[2*p], o0[2*p+1]);
            o1p[p] = pack2(o1[2*p], o1[2*p+1]);
            o2p[p] = pack2(o2[2*p], o2[2*p+1]);
        }
        const ull* cp = reinterpret_cast<const ull*>(cf2);
        #pragma unroll 4
        for (int c = 0; c < RES; c++) {
            ull af0 = cp[C_AF0+c], af1 = cp[C_AF1+c], af2 = cp[C_AF2+c], bfa = cp[C_BFA+c];
            ull ag0 = cp[C_AG0+c], ag1 = cp[C_AG1+c], ag2 = cp[C_AG2+c], bga = cp[C_BGA+c];
            float wo = cf2[C_WO+c].x;
            uint2 pk;
            #pragma unroll
            for (int p = 0; p < 2; p++) {
                ull pf2 = fma2(af0, o0p[p], fma2(af1, o1p[p], fma2(af2, o2p[p], bfa)));
                ull pg2 = fma2(ag0, o0p[p], fma2(ag1, o1p[p], fma2(ag2, o2p[p], bga)));
                float pf0, pf1, pg0, pg1;
                unpack2(pf2, pf0, pf1);
                unpack2(pg2, pg0, pg1);
                float gt0 = tanh_hw(pf0) * fmaf(0.5f, tanh_hw(pg0), 0.5f);
                float gt1 = tanh_hw(pf1) * fmaf(0.5f, tanh_hw(pg1), 0.5f);
                acc[2*p]   = fmaf(wo, gt0, acc[2*p]);
                acc[2*p+1] = fmaf(wo, gt1, acc[2*p+1]);
                __half2 h = __floats2half2_rn(gt0, gt1);
                if (p == 0) pk.x = *reinterpret_cast<uint32_t*>(&h);
                else        pk.y = *reinterpret_cast<uint32_t*>(&h);
            }
            *reinterpret_cast<uint2*>(&gp[(size_t)c*NTOT + base]) = pk;
        }
    } else {
        #pragma unroll 4
        for (int c = 0; c < RES; c++) {
            float af0 = cf2[C_AF0+c].x, af1 = cf2[C_AF1+c].x, af2 = cf2[C_AF2+c].x, bfa = cf2[C_BFA+c].x;
            float ag0 = cf2[C_AG0+c].x, ag1 = cf2[C_AG1+c].x, ag2 = cf2[C_AG2+c].x, bga = cf2[C_BGA+c].x;
            float wo  = cf2[C_WO+c].x;
            float gt[AU];
            #pragma unroll
            for (int u = 0; u < AU; u++) {
                float pf = fmaf(af0, o0[u], fmaf(af1, o1[u], fmaf(af2, o2[u], bfa)));
                float pg = fmaf(ag0, o0[u], fmaf(ag1, o1[u], fmaf(ag2, o2[u], bga)));
                int t = tbase + u;
                if (t < 2*d) { pf -= cf2[C_DF0+c].x; pg -= cf2[C_DG0+c].x; }
                if (t < d)   { pf -= cf2[C_DF1+c].x; pg -= cf2[C_DG1+c].x; }
                float sg = fmaf(0.5f, tanh_hw(pg), 0.5f);
                gt[u] = tanh_hw(pf) * sg;
                acc[u] = fmaf(wo, gt[u], acc[u]);
            }
            __half2 h01 = __floats2half2_rn(gt[0], gt[1]);
            __half2 h23 = __floats2half2_rn(gt[2], gt[3]);
            uint2 pk;
            pk.x = *reinterpret_cast<uint32_t*>(&h01);
            pk.y = *reinterpret_cast<uint32_t*>(&h23);
            *reinterpret_cast<uint2*>(&gp[(size_t)c*NTOT + base]) = pk;
        }
    }
    {
        float4 v;
        v.x = o2[0] + acc[0] + bo;
        v.y = o2[1] + acc[1] + bo;
        v.z = o2[2] + acc[2] + bo;
        v.w = o2[3] + acc[3] + bo;
        *reinterpret_cast<float4*>(&out[base]) = v;
    }
}

// ---------------------------------------------------------------------------
// Phase B: 3-stage cp.async pipeline. D[128 samples, 64 m] per block via
// HMMA m16n8k16, fused relu/head/exp epilogue.
// ---------------------------------------------------------------------------
#define NT 128
#define KC 32
#define NSTAGE 3
#define NITER (KTOT/KC)          // 16
#define XPITCH 136   // halfs per row (272B; 68 words ≡ 4 mod 32)
#define GPITCH 72    // halfs per row (144B; 36 words ≡ 4 mod 32)
#define XBUF (KC*XPITCH)         // halfs per stage
#define GBUF (KC*GPITCH)

__device__ __forceinline__ uint32_t smem_u32(const void* p) {
    uint32_t a;
    asm("{ .reg .u64 t; cvta.to.shared.u64 t, %1; cvt.u32.u64 %0, t; }" : "=r"(a) : "l"(p));
    return a;
}
__device__ __forceinline__ void cp_async16(uint32_t dst, const void* src) {
    asm volatile("cp.async.cg.shared.global [%0], [%1], 16;" :: "r"(dst), "l"(src) : "memory");
}

__global__ void __launch_bounds__(256) phaseB_kernel(const float* __restrict__ W_sk2,
                                                     const float* __restrict__ b_sk2,
                                                     float* __restrict__ outp)
{
    __shared__ __align__(16) __half sX[NSTAGE*XBUF];   // 3*8704 B
    __shared__ __align__(16) __half sG[NSTAGE*GBUF];   // 3*4608 B

    int tid  = threadIdx.x;
    int n0   = blockIdx.x * NT;
    int warp = tid >> 5, lane = tid & 31;
    int grp  = lane >> 2, tig = lane & 3;
    int s0   = warp * 16;              // this warp's 16 samples

    uint32_t sXbase = smem_u32(sX), sGbase = smem_u32(sG);

    // staging indices (per thread): X: 2x16B, G: 1x16B
    int xk = tid >> 4, xnoct = tid & 15;           // covers k 0..15 (it0) / 16..31 (it1)
    int gk = tid >> 3, gmoct = tid & 7;            // covers k 0..31

    float c[8][4];
    #pragma unroll
    for (int a = 0; a < 8; a++)
        #pragma unroll
        for (int b = 0; b < 4; b++) c[a][b] = 0.f;

    int i8 = lane & 7, seg = lane >> 3;
    uint32_t aAddr = sXbase +
        (uint32_t)(((i8 + (seg >> 1)*8)*XPITCH + s0 + (seg & 1)*8) * 2);
    uint32_t bAddr = sGbase +
        (uint32_t)(((i8 + (seg & 1)*8)*GPITCH + (seg >> 1)*8) * 2);

    // stage issue helper (macro-like lambda)
    auto stage = [&](int it, int buf) {
        int jb = it*KC;
        uint32_t xd = sXbase + (uint32_t)((buf*XBUF)*2);
        uint32_t gd = sGbase + (uint32_t)((buf*GBUF)*2);
        cp_async16(xd + (uint32_t)((xk*XPITCH + xnoct*8)*2),
                   &g_gatedH[(size_t)(jb + xk)*NTOT + n0 + xnoct*8]);
        cp_async16(xd + (uint32_t)(((xk+16)*XPITCH + xnoct*8)*2),
                   &g_gatedH[(size_t)(jb + xk + 16)*NTOT + n0 + xnoct*8]);
        cp_async16(gd + (uint32_t)((gk*GPITCH + gmoct*8)*2),
                   &g_Gh[(jb + gk)*64 + gmoct*8]);
        asm volatile("cp.async.commit_group;" ::: "memory");
    };

    stage(0, 0);
    stage(1, 1);

    for (int it = 0; it < NITER; it++) {
        asm volatile("cp.async.wait_group 1;" ::: "memory");
        __syncthreads();
        if (it + 2 < NITER) stage(it + 2, (it + 2) % NSTAGE);
        else asm volatile("cp.async.commit_group;" ::: "memory");  // keep group count in sync

        int buf = it % NSTAGE;
        uint32_t aB = aAddr + (uint32_t)((buf*XBUF)*2);
        uint32_t bB = bAddr + (uint32_t)((buf*GBUF)*2);

        #pragma unroll
        for (int ks = 0; ks < 2; ks++) {        // 2 k-steps of 16
            uint32_t a0, a1, a2, a3;
            asm volatile("ldmatrix.sync.aligned.m8n8.x4.trans.shared.b16 {%0,%1,%2,%3}, [%4];"
                         : "=r"(a0), "=r"(a1), "=r"(a2), "=r"(a3)
                         : "r"(aB + (uint32_t)(ks*16*XPITCH*2)));
            #pragma unroll
            for (int mp = 0; mp < 4; mp++) {
                uint32_t b0, b1, b2, b3;
                asm volatile("ldmatrix.sync.aligned.m8n8.x4.trans.shared.b16 {%0,%1,%2,%3}, [%4];"
                             : "=r"(b0), "=r"(b1), "=r"(b2), "=r"(b3)
                             : "r"(bB + (uint32_t)((ks*16*GPITCH + mp*16)*2)));
                asm volatile("mma.sync.aligned.m16n8k16.row.col.f32.f16.f16.f32 "
                             "{%0,%1,%2,%3}, {%4,%5,%6,%7}, {%8,%9}, {%0,%1,%2,%3};"
                             : "+f"(c[2*mp][0]), "+f"(c[2*mp][1]), "+f"(c[2*mp][2]), "+f"(c[2*mp][3])
                             : "r"(a0), "r"(a1), "r"(a2), "r"(a3), "r"(b0), "r"(b1));
                asm volatile("mma.sync.aligned.m16n8k16.row.col.f32.f16.f16.f32 "
                             "{%0,%1,%2,%3}, {%4,%5,%6,%7}, {%8,%9}, {%0,%1,%2,%3};"
                             : "+f"(c[2*mp+1][0]), "+f"(c[2*mp+1][1]), "+f"(c[2*mp+1][2]), "+f"(c[2*mp+1][3])
                             : "r"(a0), "r"(a1), "r"(a2), "r"(a3), "r"(b2), "r"(b3));
            }
        }
        __syncthreads();
    }

    float pa0 = 0.f, pa1 = 0.f, pb0 = 0.f, pb1 = 0.f;
    #pragma unroll
    for (int mt = 0; mt < 8; mt++) {
        int m = mt*8 + tig*2;
        float c1a = g_C1[m],     c1b = g_C1[m+1];
        float w0a = W_sk2[m],    w0b = W_sk2[m+1];
        float w1a = W_sk2[64+m], w1b = W_sk2[64+m+1];
        float v;
        v = fmaxf(c[mt][0] + c1a, 0.f); pa0 = fmaf(w0a, v, pa0); pa1 = fmaf(w1a, v, pa1);
        v = fmaxf(c[mt][1] + c1b, 0.f); pa0 = fmaf(w0b, v, pa0); pa1 = fmaf(w1b, v, pa1);
        v = fmaxf(c[mt][2] + c1a, 0.f); pb0 = fmaf(w0a, v, pb0); pb1 = fmaf(w1a, v, pb1);
        v = fmaxf(c[mt][3] + c1b, 0.f); pb0 = fmaf(w0b, v, pb0); pb1 = fmaf(w1b, v, pb1);
    }
    #pragma unroll
    for (int off = 1; off <= 2; off <<= 1) {
        pa0 += __shfl_xor_sync(0xFFFFFFFFu, pa0, off);
        pa1 += __shfl_xor_sync(0xFFFFFFFFu, pa1, off);
        pb0 += __shfl_xor_sync(0xFFFFFFFFu, pb0, off);
        pb1 += __shfl_xor_sync(0xFFFFFFFFu, pb1, off);
    }
    if (tig == 0) {
        int na = n0 + s0 + grp;
        int nb = na + 8;
        outp[na]        = pa0 + b_sk2[0];
        outp[NTOT + na] = __expf(0.5f*(pa1 + b_sk2[1]));
        outp[nb]        = pb0 + b_sk2[0];
        outp[NTOT + nb] = __expf(0.5f*(pb1 + b_sk2[1]));
    }
}

// ---------------------------------------------------------------------------
extern "C" void kernel_launch(void* const* d_in, const int* in_sizes, int n_in,
                              void* d_out, int out_size)
{
    const float* x     = (const float*)d_in[0];
    const float* W_in  = (const float*)d_in[1];
    const float* b_in  = (const float*)d_in[2];
    const float* W_f   = (const float*)d_in[3];
    const float* b_f   = (const float*)d_in[4];
    const float* W_g   = (const float*)d_in[5];
    const float* b_g   = (const float*)d_in[6];
    const float* W_s   = (const float*)d_in[7];
    const float* b_s   = (const float*)d_in[8];
    const float* W_o   = (const float*)d_in[9];
    const float* b_o   = (const float*)d_in[10];
    const float* W_sk1 = (const float*)d_in[11];
    const float* b_sk1 = (const float*)d_in[12];
    const float* W_sk2 = (const float*)d_in[13];
    const float* b_sk2 = (const float*)d_in[14];
    float* outp = (float*)d_out;

    precompute_layer<<<NLAYER, 32>>>(W_in, b_in, W_f, b_f, W_g, b_g, W_o, b_o);
    precompute_skip<<<128, 256>>>(W_s, b_s, W_sk1, b_sk1);

    for (int i = 0; i < NLAYER; i++) {
        int d = 1 << (i & 7);
        layer_kernel<<<NTOT/(256*AU), 256>>>(x, i, d);
    }
    phaseB_kernel<<<NTOT/NT, 256>>>(W_sk2, b_sk2, outp);
}

// round 16
// speedup vs baseline: 1.7256x; 1.0184x over previous
#include <cuda_runtime.h>
#include <cuda_fp16.h>
#include <cstdint>

#define NLAYER 16
#define BATCH 8
#define TLEN 65536
#define NTOT (BATCH*TLEN)        // 524288
#define RES 32
#define KTOT (NLAYER*RES)        // 512

typedef unsigned long long ull;

// per-layer coefficient layout (floats), stride 420
// NOTE: all *G* entries are pre-halved (sigmoid-via-tanh trick)
#define C_AF0 0
#define C_AF1 32
#define C_AF2 64
#define C_BFA 96
#define C_DF0 128
#define C_DF1 160
#define C_AG0 192
#define C_AG1 224
#define C_AG2 256
#define C_BGA 288
#define C_DG0 320
#define C_DG1 352
#define C_WO  384
#define C_BO  416
#define C_STRIDE 420

__device__ float  g_coef[NLAYER*C_STRIDE];
__device__ __half g_Gh[KTOT*64];     // folded (W_sk1 @ W_s_cat), fp16, layout [j][m]
__device__ float  g_C1[64];          // folded bias into pre-relu
__device__ float  g_bufA[NTOT];
__device__ float  g_bufB[NTOT];
__device__ __half g_gatedH[(size_t)KTOT*NTOT];   // 512 MiB scratch, layout [j][n]

// ---------------------------------------------------------------------------
// Precompute 1: collapse per-layer convs onto the scalar residual stream.
// ---------------------------------------------------------------------------
__global__ void precompute_layer(const float* __restrict__ W_in, const float* __restrict__ b_in,
                                 const float* __restrict__ W_f,  const float* __restrict__ b_f,
                                 const float* __restrict__ W_g,  const float* __restrict__ b_g,
                                 const float* __restrict__ W_o,  const float* __restrict__ b_o)
{
    int i = blockIdx.x;      // layer
    int c = threadIdx.x;     // out channel (32)
    float af[3] = {0,0,0}, df[3] = {0,0,0};
    float ag[3] = {0,0,0}, dg[3] = {0,0,0};
    for (int cin = 0; cin < 32; cin++) {
        float wi = W_in[i*32 + cin];
        float bi = b_in[i*32 + cin];
        #pragma unroll
        for (int k = 0; k < 3; k++) {
            float wf = W_f[((i*32 + c)*32 + cin)*3 + k];
            float wg = W_g[((i*32 + c)*32 + cin)*3 + k];
            af[k] = fmaf(wf, wi, af[k]);
            df[k] = fmaf(wf, bi, df[k]);
            ag[k] = fmaf(wg, wi, ag[k]);
            dg[k] = fmaf(wg, bi, dg[k]);
        }
    }
    float* cf = g_coef + i*C_STRIDE;
    cf[C_AF0+c] = af[0]; cf[C_AF1+c] = af[1]; cf[C_AF2+c] = af[2];
    cf[C_BFA+c] = b_f[i*32 + c] + df[0] + df[1] + df[2];
    cf[C_DF0+c] = df[0]; cf[C_DF1+c] = df[1];
    cf[C_AG0+c] = 0.5f*ag[0]; cf[C_AG1+c] = 0.5f*ag[1]; cf[C_AG2+c] = 0.5f*ag[2];
    cf[C_BGA+c] = 0.5f*(b_g[i*32 + c] + dg[0] + dg[1] + dg[2]);
    cf[C_DG0+c] = 0.5f*dg[0]; cf[C_DG1+c] = 0.5f*dg[1];
    cf[C_WO +c] = W_o[i*32 + c];
    if (c == 0) cf[C_BO] = b_o[i];
}

// ---------------------------------------------------------------------------
// Precompute 2: fold skip path to fp16 G and fp32 c1.
// ---------------------------------------------------------------------------
__global__ void precompute_skip(const float* __restrict__ W_s,   const float* __restrict__ b_s,
                                const float* __restrict__ W_sk1, const float* __restrict__ b_sk1)
{
    int gid = blockIdx.x*blockDim.x + threadIdx.x;
    if (gid < KTOT*64) {
        int j = gid >> 6, m = gid & 63;
        int i = j >> 5, c = j & 31;
        float acc = 0.f;
        for (int o = 0; o < 64; o++)
            acc = fmaf(W_sk1[m*64 + o], W_s[(i*64 + o)*32 + c], acc);
        g_Gh[j*64 + m] = __float2half_rn(acc);
    }
    if (gid < 64) {
        int m = gid;
        float acc = b_sk1[m];
        for (int o = 0; o < 64; o++) {
            float bs = 0.f;
            for (int i2 = 0; i2 < NLAYER; i2++) bs += b_s[i2*64 + o];
            acc = fmaf(W_sk1[m*64 + o], bs, acc);
        }
        g_C1[m] = acc;
    }
}

// ---------------------------------------------------------------------------
// Phase A helpers
// ---------------------------------------------------------------------------
__device__ __forceinline__ float tanh_hw(float x) {
    float y;
    asm("tanh.approx.f32 %0, %1;" : "=f"(y) : "f"(x));
    return y;
}
__device__ __forceinline__ ull pack2(float a, float b) {
    ull r;
    asm("mov.b64 %0, {%1,%2};" : "=l"(r) : "r"(__float_as_uint(a)), "r"(__float_as_uint(b)));
    return r;
}
__device__ __forceinline__ void unpack2(ull p, float& a, float& b) {
    unsigned lo, hi;
    asm("mov.b64 {%0,%1}, %2;" : "=r"(lo), "=r"(hi) : "l"(p));
    a = __uint_as_float(lo); b = __uint_as_float(hi);
}
__device__ __forceinline__ ull fma2(ull a, ull b, ull c) {
    ull d;
    asm("fma.rn.f32x2 %0, %1, %2, %3;" : "=l"(d) : "l"(a), "l"(b), "l"(c));
    return d;
}

// ---------------------------------------------------------------------------
// Phase A: collapsed rank-1 form, f32x2 packed FMAs (coefs duplicated in smem),
// gated = tanh(pf) * (0.5*tanh(pg_half) + 0.5), packed 4B fp16 stores.
// AU=2: one f32x2 pair per thread, 1024 blocks -> ~7 blocks/SM (latency hiding).
// ---------------------------------------------------------------------------
#define AU 2
__global__ void __launch_bounds__(256) layer_kernel(const float* __restrict__ x, int layer, int d)
{
    __shared__ __align__(8) float2 cf2[C_STRIDE];   // each coef duplicated in .x/.y
    {
        const float* gc = g_coef + layer*C_STRIDE;
        for (int idx = threadIdx.x; idx < C_STRIDE; idx += 256) {
            float v = gc[idx];
            cf2[idx] = make_float2(v, v);
        }
    }
    __syncthreads();

    const float* in = (layer == 0) ? x : ((layer & 1) ? g_bufA : g_bufB);
    float* out = (layer & 1) ? g_bufB : g_bufA;
    __half* gp = g_gatedH + (size_t)layer*RES*NTOT;

    int base = (blockIdx.x*256 + threadIdx.x)*AU;   // contiguous pair
    int tbase = base & (TLEN - 1);                  // pair never crosses batch row

    float o0[AU], o1[AU], o2[AU], acc[AU];
    {
        float2 v = *reinterpret_cast<const float2*>(&in[base]);
        o2[0] = v.x; o2[1] = v.y;
    }
    #pragma unroll
    for (int u = 0; u < AU; u++) {
        int n = base + u, t = tbase + u;
        o1[u] = (t >= d)   ? in[n - d]   : 0.f;
        o0[u] = (t >= 2*d) ? in[n - 2*d] : 0.f;
        acc[u] = 0.f;
    }
    float bo = cf2[C_BO].x;
    bool edge = (tbase < 2*d);   // rare

    if (!edge) {
        ull o0p = pack2(o0[0], o0[1]);
        ull o1p = pack2(o1[0], o1[1]);
        ull o2p = pack2(o2[0], o2[1]);
        const ull* cp = reinterpret_cast<const ull*>(cf2);
        #pragma unroll 8
        for (int c = 0; c < RES; c++) {
            ull af0 = cp[C_AF0+c], af1 = cp[C_AF1+c], af2 = cp[C_AF2+c], bfa = cp[C_BFA+c];
            ull ag0 = cp[C_AG0+c], ag1 = cp[C_AG1+c], ag2 = cp[C_AG2+c], bga = cp[C_BGA+c];
            float wo = cf2[C_WO+c].x;
            ull pf2 = fma2(af0, o0p, fma2(af1, o1p, fma2(af2, o2p, bfa)));
            ull pg2 = fma2(ag0, o0p, fma2(ag1, o1p, fma2(ag2, o2p, bga)));
            float pf0, pf1, pg0, pg1;
            unpack2(pf2, pf0, pf1);
            unpack2(pg2, pg0, pg1);
            float gt0 = tanh_hw(pf0) * fmaf(0.5f, tanh_hw(pg0), 0.5f);
            float gt1 = tanh_hw(pf1) * fmaf(0.5f, tanh_hw(pg1), 0.5f);
            acc[0] = fmaf(wo, gt0, acc[0]);
            acc[1] = fmaf(wo, gt1, acc[1]);
            __half2 h = __floats2half2_rn(gt0, gt1);
            *reinterpret_cast<uint32_t*>(&gp[(size_t)c*NTOT + base]) =
                *reinterpret_cast<uint32_t*>(&h);
        }
    } else {
        #pragma unroll 8
        for (int c = 0; c < RES; c++) {
            float af0 = cf2[C_AF0+c].x, af1 = cf2[C_AF1+c].x, af2 = cf2[C_AF2+c].x, bfa = cf2[C_BFA+c].x;
            float ag0 = cf2[C_AG0+c].x, ag1 = cf2[C_AG1+c].x, ag2 = cf2[C_AG2+c].x, bga = cf2[C_BGA+c].x;
            float wo  = cf2[C_WO+c].x;
            float gt[AU];
            #pragma unroll
            for (int u = 0; u < AU; u++) {
                float pf = fmaf(af0, o0[u], fmaf(af1, o1[u], fmaf(af2, o2[u], bfa)));
                float pg = fmaf(ag0, o0[u], fmaf(ag1, o1[u], fmaf(ag2, o2[u], bga)));
                int t = tbase + u;
                if (t < 2*d) { pf -= cf2[C_DF0+c].x; pg -= cf2[C_DG0+c].x; }
                if (t < d)   { pf -= cf2[C_DF1+c].x; pg -= cf2[C_DG1+c].x; }
                float sg = fmaf(0.5f, tanh_hw(pg), 0.5f);
                gt[u] = tanh_hw(pf) * sg;
                acc[u] = fmaf(wo, gt[u], acc[u]);
            }
            __half2 h = __floats2half2_rn(gt[0], gt[1]);
            *reinterpret_cast<uint32_t*>(&gp[(size_t)c*NTOT + base]) =
                *reinterpret_cast<uint32_t*>(&h);
        }
    }
    {
        float2 v;
        v.x = o2[0] + acc[0] + bo;
        v.y = o2[1] + acc[1] + bo;
        *reinterpret_cast<float2*>(&out[base]) = v;
    }
}

// ---------------------------------------------------------------------------
// Phase B: 3-stage cp.async pipeline. D[128 samples, 64 m] per block via
// HMMA m16n8k16, fused relu/head/exp epilogue.
// ---------------------------------------------------------------------------
#define NT 128
#define KC 32
#define NSTAGE 3
#define NITER (KTOT/KC)          // 16
#define XPITCH 136   // halfs per row (272B; 68 words ≡ 4 mod 32)
#define GPITCH 72    // halfs per row (144B; 36 words ≡ 4 mod 32)
#define XBUF (KC*XPITCH)         // halfs per stage
#define GBUF (KC*GPITCH)

__device__ __forceinline__ uint32_t smem_u32(const void* p) {
    uint32_t a;
    asm("{ .reg .u64 t; cvta.to.shared.u64 t, %1; cvt.u32.u64 %0, t; }" : "=r"(a) : "l"(p));
    return a;
}
__device__ __forceinline__ void cp_async16(uint32_t dst, const void* src) {
    asm volatile("cp.async.cg.shared.global [%0], [%1], 16;" :: "r"(dst), "l"(src) : "memory");
}

__global__ void __launch_bounds__(256) phaseB_kernel(const float* __restrict__ W_sk2,
                                                     const float* __restrict__ b_sk2,
                                                     float* __restrict__ outp)
{
    __shared__ __align__(16) __half sX[NSTAGE*XBUF];   // 3*8704 B
    __shared__ __align__(16) __half sG[NSTAGE*GBUF];   // 3*4608 B

    int tid  = threadIdx.x;
    int n0   = blockIdx.x * NT;
    int warp = tid >> 5, lane = tid & 31;
    int grp  = lane >> 2, tig = lane & 3;
    int s0   = warp * 16;              // this warp's 16 samples

    uint32_t sXbase = smem_u32(sX), sGbase = smem_u32(sG);

    int xk = tid >> 4, xnoct = tid & 15;
    int gk = tid >> 3, gmoct = tid & 7;

    float c[8][4];
    #pragma unroll
    for (int a = 0; a < 8; a++)
        #pragma unroll
        for (int b = 0; b < 4; b++) c[a][b] = 0.f;

    int i8 = lane & 7, seg = lane >> 3;
    uint32_t aAddr = sXbase +
        (uint32_t)(((i8 + (seg >> 1)*8)*XPITCH + s0 + (seg & 1)*8) * 2);
    uint32_t bAddr = sGbase +
        (uint32_t)(((i8 + (seg & 1)*8)*GPITCH + (seg >> 1)*8) * 2);

    auto stage = [&](int it, int buf) {
        int jb = it*KC;
        uint32_t xd = sXbase + (uint32_t)((buf*XBUF)*2);
        uint32_t gd = sGbase + (uint32_t)((buf*GBUF)*2);
        cp_async16(xd + (uint32_t)((xk*XPITCH + xnoct*8)*2),
                   &g_gatedH[(size_t)(jb + xk)*NTOT + n0 + xnoct*8]);
        cp_async16(xd + (uint32_t)(((xk+16)*XPITCH + xnoct*8)*2),
                   &g_gatedH[(size_t)(jb + xk + 16)*NTOT + n0 + xnoct*8]);
        cp_async16(gd + (uint32_t)((gk*GPITCH + gmoct*8)*2),
                   &g_Gh[(jb + gk)*64 + gmoct*8]);
        asm volatile("cp.async.commit_group;" ::: "memory");
    };

    stage(0, 0);
    stage(1, 1);

    for (int it = 0; it < NITER; it++) {
        asm volatile("cp.async.wait_group 1;" ::: "memory");
        __syncthreads();
        if (it + 2 < NITER) stage(it + 2, (it + 2) % NSTAGE);
        else asm volatile("cp.async.commit_group;" ::: "memory");

        int buf = it % NSTAGE;
        uint32_t aB = aAddr + (uint32_t)((buf*XBUF)*2);
        uint32_t bB = bAddr + (uint32_t)((buf*GBUF)*2);

        #pragma unroll
        for (int ks = 0; ks < 2; ks++) {
            uint32_t a0, a1, a2, a3;
            asm volatile("ldmatrix.sync.aligned.m8n8.x4.trans.shared.b16 {%0,%1,%2,%3}, [%4];"
                         : "=r"(a0), "=r"(a1), "=r"(a2), "=r"(a3)
                         : "r"(aB + (uint32_t)(ks*16*XPITCH*2)));
            #pragma unroll
            for (int mp = 0; mp < 4; mp++) {
                uint32_t b0, b1, b2, b3;
                asm volatile("ldmatrix.sync.aligned.m8n8.x4.trans.shared.b16 {%0,%1,%2,%3}, [%4];"
                             : "=r"(b0), "=r"(b1), "=r"(b2), "=r"(b3)
                             : "r"(bB + (uint32_t)((ks*16*GPITCH + mp*16)*2)));
                asm volatile("mma.sync.aligned.m16n8k16.row.col.f32.f16.f16.f32 "
                             "{%0,%1,%2,%3}, {%4,%5,%6,%7}, {%8,%9}, {%0,%1,%2,%3};"
                             : "+f"(c[2*mp][0]), "+f"(c[2*mp][1]), "+f"(c[2*mp][2]), "+f"(c[2*mp][3])
                             : "r"(a0), "r"(a1), "r"(a2), "r"(a3), "r"(b0), "r"(b1));
                asm volatile("mma.sync.aligned.m16n8k16.row.col.f32.f16.f16.f32 "
                             "{%0,%1,%2,%3}, {%4,%5,%6,%7}, {%8,%9}, {%0,%1,%2,%3};"
                             : "+f"(c[2*mp+1][0]), "+f"(c[2*mp+1][1]), "+f"(c[2*mp+1][2]), "+f"(c[2*mp+1][3])
                             : "r"(a0), "r"(a1), "r"(a2), "r"(a3), "r"(b2), "r"(b3));
            }
        }
        __syncthreads();
    }

    float pa0 = 0.f, pa1 = 0.f, pb0 = 0.f, pb1 = 0.f;
    #pragma unroll
    for (int mt = 0; mt < 8; mt++) {
        int m = mt*8 + tig*2;
        float c1a = g_C1[m],     c1b = g_C1[m+1];
        float w0a = W_sk2[m],    w0b = W_sk2[m+1];
        float w1a = W_sk2[64+m], w1b = W_sk2[64+m+1];
        float v;
        v = fmaxf(c[mt][0] + c1a, 0.f); pa0 = fmaf(w0a, v, pa0); pa1 = fmaf(w1a, v, pa1);
        v = fmaxf(c[mt][1] + c1b, 0.f); pa0 = fmaf(w0b, v, pa0); pa1 = fmaf(w1b, v, pa1);
        v = fmaxf(c[mt][2] + c1a, 0.f); pb0 = fmaf(w0a, v, pb0); pb1 = fmaf(w1a, v, pb1);
        v = fmaxf(c[mt][3] + c1b, 0.f); pb0 = fmaf(w0b, v, pb0); pb1 = fmaf(w1b, v, pb1);
    }
    #pragma unroll
    for (int off = 1; off <= 2; off <<= 1) {
        pa0 += __shfl_xor_sync(0xFFFFFFFFu, pa0, off);
        pa1 += __shfl_xor_sync(0xFFFFFFFFu, pa1, off);
        pb0 += __shfl_xor_sync(0xFFFFFFFFu, pb0, off);
        pb1 += __shfl_xor_sync(0xFFFFFFFFu, pb1, off);
    }
    if (tig == 0) {
        int na = n0 + s0 + grp;
        int nb = na + 8;
        outp[na]        = pa0 + b_sk2[0];
        outp[NTOT + na] = __expf(0.5f*(pa1 + b_sk2[1]));
        outp[nb]        = pb0 + b_sk2[0];
        outp[NTOT + nb] = __expf(0.5f*(pb1 + b_sk2[1]));
    }
}

// ---------------------------------------------------------------------------
extern "C" void kernel_launch(void* const* d_in, const int* in_sizes, int n_in,
                              void* d_out, int out_size)
{
    const float* x     = (const float*)d_in[0];
    const float* W_in  = (const float*)d_in[1];
    const float* b_in  = (const float*)d_in[2];
    const float* W_f   = (const float*)d_in[3];
    const float* b_f   = (const float*)d_in[4];
    const float* W_g   = (const float*)d_in[5];
    const float* b_g   = (const float*)d_in[6];
    const float* W_s   = (const float*)d_in[7];
    const float* b_s   = (const float*)d_in[8];
    const float* W_o   = (const float*)d_in[9];
    const float* b_o   = (const float*)d_in[10];
    const float* W_sk1 = (const float*)d_in[11];
    const float* b_sk1 = (const float*)d_in[12];
    const float* W_sk2 = (const float*)d_in[13];
    const float* b_sk2 = (const float*)d_in[14];
    float* outp = (float*)d_out;

    precompute_layer<<<NLAYER, 32>>>(W_in, b_in, W_f, b_f, W_g, b_g, W_o, b_o);
    precompute_skip<<<128, 256>>>(W_s, b_s, W_sk1, b_sk1);

    for (int i = 0; i < NLAYER; i++) {
        int d = 1 << (i & 7);
        layer_kernel<<<NTOT/(256*AU), 256>>>(x, i, d);
    }
    phaseB_kernel<<<NTOT/NT, 256>>>(W_sk2, b_sk2, outp);
}